// round 13
// baseline (speedup 1.0000x reference)
#include <cuda_runtime.h>
#include <math.h>
#include <stdint.h>

#define TPB1 128
#define TPB2 1024
#define IDX_CAP (1 << 22)

// Static device scratch (allocation-free).
__device__ int    g_idx[IDX_CAP];    // per-batch compacted leaf indices (local)
__device__ int    g_cnt[1024];       // per-batch leaf count
__device__ float4 g_part4[8192];     // per-MLP-block partials {Σs, Σ(s-.5)², nSel, na}

// ---------------------------------------------------------------------------
// leaf_mask dtype detect (jax bool is dtype-ambiguous), parallel across block:
//   int32 0/1 -> 1, float32 0/1.0 -> 2, uint8 bool -> 0.
// ---------------------------------------------------------------------------
__device__ __forceinline__ int detect_mask_mode_par(const void* m, int tid, int nw) {
    int ok = 1, okf = 1;
    if (tid < nw) {
        unsigned int v = ((const unsigned int*)m)[tid];
        ok  = (v <= 1u);
        okf = (v == 0u || v == 0x3F800000u);
    }
    int allBin   = __syncthreads_and(ok);
    int allFloat = __syncthreads_and(okf);
    return allBin ? 1 : (allFloat ? 2 : 0);
}

__device__ __forceinline__ int read_mask_i(const void* m, size_t i, int mode) {
    if (mode == 1) return ((const int*)m)[i] != 0;
    if (mode == 2) return ((const float*)m)[i] != 0.0f;
    return ((const unsigned char*)m)[i] != 0;
}

// ---------------------------------------------------------------------------
// Kernel A: per-batch stable compaction of leaf indices (ascending order via
// contiguous per-thread chunks + block prefix scan). Also zero-fills bp for
// non-leaf points (MLP writes the leaf ones). grid = B, block = 1024.
// ---------------------------------------------------------------------------
__global__ void __launch_bounds__(TPB2) compact_kernel(
    const void* __restrict__ mask, float* __restrict__ bp, int N)
{
    __shared__ int sWS[32];
    __shared__ int sWB[32];
    __shared__ int sTot;

    int tid = threadIdx.x;
    int b = blockIdx.x;
    size_t base = (size_t)b * N;

    int mode = detect_mask_mode_par(mask, tid, 256);   // has barriers

    int per = (N + TPB2 - 1) / TPB2;
    int i0 = tid * per;
    int c = 0;
    for (int u = 0; u < per; u++) {
        int i = i0 + u;
        if (i < N && read_mask_i(mask, base + i, mode)) c++;
    }

    // Block exclusive scan of c
    int lane = tid & 31, warp = tid >> 5;
    int incl = c;
    #pragma unroll
    for (int o = 1; o < 32; o <<= 1) {
        int t = __shfl_up_sync(0xFFFFFFFFu, incl, o);
        if (lane >= o) incl += t;
    }
    if (lane == 31) sWS[warp] = incl;
    __syncthreads();
    if (warp == 0) {
        int v = sWS[lane];
        int iv = v;
        #pragma unroll
        for (int o = 1; o < 32; o <<= 1) {
            int t = __shfl_up_sync(0xFFFFFFFFu, iv, o);
            if (lane >= o) iv += t;
        }
        sWB[lane] = iv - v;
        if (lane == 31) sTot = iv;
    }
    __syncthreads();

    // Scatter (re-read mask; L1/L2 hot) + zero-fill non-leaf bp
    int r = sWB[warp] + (incl - c);
    for (int u = 0; u < per; u++) {
        int i = i0 + u;
        if (i < N) {
            if (read_mask_i(mask, base + i, mode)) g_idx[base + r++] = i;
            else                                   bp[base + i] = 0.0f;
        }
    }
    if (tid == 0) g_cnt[b] = sTot;
}

// ---------------------------------------------------------------------------
// Kernel B: MLP over compacted leaf points only (dense warps).
//   x = [features(64), xyz(3)], h1 = relu(x W1^T + b1),
//   h2 = relu(h1 W2^T + b2), s = sigmoid(h2 W3^T + b3); bp[leaf] = s.
// Emits per-block partials {Σs, Σ(s-0.5)², #(s>0.7), na}.
// Shared: transposed W1/W2 (float4 broadcast rows), full 64-feature staging
// rows at stride 65 (gcd(65,32)=1 -> conflict-free), compacted index list.
// ---------------------------------------------------------------------------
__global__ void __launch_bounds__(TPB1) mlp_kernel(
    const float* __restrict__ points, const float* __restrict__ features,
    const float* __restrict__ W1, const float* __restrict__ b1,
    const float* __restrict__ W2, const float* __restrict__ b2,
    const float* __restrict__ W3, const float* __restrict__ b3,
    float* __restrict__ bp, int N, int bpB)
{
    extern __shared__ float smem_dyn[];
    float* sW1T = smem_dyn;                 // 67*64 = 4288 (16B-aligned rows)
    float* sW2T = sW1T + 67 * 64;           // 64*32 = 2048
    float* sB1  = sW2T + 64 * 32;           // 64
    float* sB2  = sB1 + 64;                 // 32
    float* sW3  = sB2 + 32;                 // 32
    float* sX   = sW3 + 32;                 // 128*65 = 8320
    int*   sIdx = (int*)(sX + TPB1 * 65);   // 128

    __shared__ float sb3v;
    __shared__ float3 sPart[TPB1 / 32];

    int tid = threadIdx.x;
    int batch = blockIdx.x / bpB;
    int chunk = blockIdx.x % bpB;

    int cnt = g_cnt[batch];
    int start = chunk * TPB1;
    if (start >= cnt) {                      // inactive block: zero partial
        if (tid == 0) g_part4[blockIdx.x] = make_float4(0.f, 0.f, 0.f, 0.f);
        return;
    }
    int na = min(TPB1, cnt - start);
    size_t base = (size_t)batch * N;

    if (tid < na) sIdx[tid] = g_idx[base + start + tid];
    if (tid == 0) sb3v = b3[0];

    // Weights (coalesced reads, transposed stores)
    for (int idx = tid; idx < 64 * 67; idx += TPB1) {
        int j = idx / 67, k = idx % 67;
        sW1T[k * 64 + j] = W1[idx];
    }
    for (int idx = tid; idx < 32 * 64; idx += TPB1) {
        int i = idx >> 6, j = idx & 63;
        sW2T[j * 32 + i] = W2[idx];
    }
    if (tid < 64) sB1[tid] = b1[tid];
    if (tid < 32) { sB2[tid] = b2[tid]; sW3[tid] = W3[tid]; }
    __syncthreads();   // sIdx visible for staging

    // Stage full 64-dim feature rows of the gathered points (float4 loads,
    // 16 threads cover one 256B row -> coalesced per row)
    for (int idx = tid; idx < na * 16; idx += TPB1) {
        int r = idx >> 4, c4 = idx & 15;
        const float4 v = ((const float4*)(features + (base + sIdx[r]) * 64))[c4];
        float* d = sX + r * 65 + c4 * 4;
        d[0] = v.x; d[1] = v.y; d[2] = v.z; d[3] = v.w;
    }
    __syncthreads();

    float s = 0.0f;
    int active = (tid < na);
    if (active) {
        const float* row = sX + tid * 65;
        int g = sIdx[tid];

        float h1[64];
        #pragma unroll
        for (int j = 0; j < 64; j++) h1[j] = sB1[j];

        #pragma unroll 4
        for (int k = 0; k < 64; k++) {
            float xk = row[k];
            const float4* w4 = (const float4*)&sW1T[k * 64];
            #pragma unroll
            for (int q = 0; q < 16; q++) {
                float4 w = w4[q];
                h1[4 * q + 0] = fmaf(xk, w.x, h1[4 * q + 0]);
                h1[4 * q + 1] = fmaf(xk, w.y, h1[4 * q + 1]);
                h1[4 * q + 2] = fmaf(xk, w.z, h1[4 * q + 2]);
                h1[4 * q + 3] = fmaf(xk, w.w, h1[4 * q + 3]);
            }
        }
        // xyz tail (k = 64..66)
        float p0 = points[(base + g) * 3 + 0];
        float p1 = points[(base + g) * 3 + 1];
        float p2 = points[(base + g) * 3 + 2];
        #pragma unroll
        for (int k = 0; k < 3; k++) {
            float xk = (k == 0) ? p0 : (k == 1) ? p1 : p2;
            const float4* w4 = (const float4*)&sW1T[(64 + k) * 64];
            #pragma unroll
            for (int q = 0; q < 16; q++) {
                float4 w = w4[q];
                h1[4 * q + 0] = fmaf(xk, w.x, h1[4 * q + 0]);
                h1[4 * q + 1] = fmaf(xk, w.y, h1[4 * q + 1]);
                h1[4 * q + 2] = fmaf(xk, w.z, h1[4 * q + 2]);
                h1[4 * q + 3] = fmaf(xk, w.w, h1[4 * q + 3]);
            }
        }

        // Layer 2: 64 -> 32 (fully unrolled; h1 stays in registers)
        float h2[32];
        #pragma unroll
        for (int i = 0; i < 32; i++) h2[i] = sB2[i];
        #pragma unroll
        for (int j = 0; j < 64; j++) {
            float hj = fmaxf(h1[j], 0.0f);
            const float4* w4 = (const float4*)&sW2T[j * 32];
            #pragma unroll
            for (int q = 0; q < 8; q++) {
                float4 w = w4[q];
                h2[4 * q + 0] = fmaf(hj, w.x, h2[4 * q + 0]);
                h2[4 * q + 1] = fmaf(hj, w.y, h2[4 * q + 1]);
                h2[4 * q + 2] = fmaf(hj, w.z, h2[4 * q + 2]);
                h2[4 * q + 3] = fmaf(hj, w.w, h2[4 * q + 3]);
            }
        }

        // Layer 3 + sigmoid
        float acc = sb3v;
        #pragma unroll
        for (int i = 0; i < 32; i++) acc = fmaf(fmaxf(h2[i], 0.0f), sW3[i], acc);
        s = 1.0f / (1.0f + expf(-acc));
        bp[base + g] = s;        // mask == 1 for compacted points
    }

    // Per-block partials: {Σs, Σ(s-0.5)², #(s>0.7)} over active lanes
    {
        float a  = active ? s : 0.0f;
        float d  = active ? (s - 0.5f) : 0.0f;
        float sq = d * d;
        float ns = (active && s > 0.7f) ? 1.0f : 0.0f;
        #pragma unroll
        for (int o = 16; o > 0; o >>= 1) {
            a  += __shfl_down_sync(0xFFFFFFFFu, a, o);
            sq += __shfl_down_sync(0xFFFFFFFFu, sq, o);
            ns += __shfl_down_sync(0xFFFFFFFFu, ns, o);
        }
        int w = tid >> 5, l = tid & 31;
        if (l == 0) sPart[w] = make_float3(a, sq, ns);
        __syncthreads();
        if (tid == 0) {
            float sa = 0.f, sk = 0.f, sn = 0.f;
            #pragma unroll
            for (int ww = 0; ww < TPB1 / 32; ww++) {
                sa += sPart[ww].x; sk += sPart[ww].y; sn += sPart[ww].z;
            }
            g_part4[blockIdx.x] = make_float4(sa, sk, sn, (float)na);
        }
    }
}

// ---------------------------------------------------------------------------
// Block-wide sum over TPB2 threads (uniform call sites only).
// ---------------------------------------------------------------------------
__device__ __forceinline__ float block_reduce_sum(float v, float* scratch) {
    #pragma unroll
    for (int o = 16; o > 0; o >>= 1) v += __shfl_down_sync(0xFFFFFFFFu, v, o);
    int w = threadIdx.x >> 5, l = threadIdx.x & 31;
    if (l == 0) scratch[w] = v;
    __syncthreads();
    if (w == 0) {
        float x = scratch[l];
        #pragma unroll
        for (int o = 16; o > 0; o >>= 1) x += __shfl_down_sync(0xFFFFFFFFu, x, o);
        if (l == 0) scratch[0] = x;
    }
    __syncthreads();
    float r = scratch[0];
    __syncthreads();
    return r;
}

// ---------------------------------------------------------------------------
// Kernel C: per-batch stats from pre-reduced partials. Light path (cnt<=5 or
// n_leaf<10) never touches the N scores except the zeroing branch. Heavy path
// (cnt>5) does the stable selection + distance variance as before.
// ---------------------------------------------------------------------------
__global__ void __launch_bounds__(TPB2) stats_kernel(
    const float* __restrict__ points, float* __restrict__ bp,
    float* __restrict__ conf, int N, int bpB)
{
    extern __shared__ unsigned char smraw[];
    int* sSel = (int*)smraw;                  // N selected indices (heavy path)
    __shared__ float sRed[32];
    __shared__ int   sIRed[32];
    __shared__ int   sCnt;

    int tid = threadIdx.x;
    int b = blockIdx.x;
    size_t base = (size_t)b * N;

    // Reduce partials
    float a = 0.f, sq = 0.f, ns = 0.f;
    for (int i = tid; i < bpB; i += TPB2) {
        float4 p = g_part4[b * bpB + i];
        a += p.x; sq += p.y; ns += p.z;
    }
    float ssum   = block_reduce_sum(a, sRed);
    float sumsq  = block_reduce_sum(sq, sRed);
    float nselF  = block_reduce_sum(ns, sRed);
    float nlf    = (float)g_cnt[b];

    if (nlf < 10.0f) {
        for (int i = tid; i < N; i += TPB2) bp[base + i] = 0.0f;
        if (tid == 0) conf[b] = 0.0f;
        return;
    }

    // clarity = masked variance via shifted sums (c = 0.5 -> no cancellation)
    float mean = ssum / nlf;
    float dm = mean - 0.5f;
    float vs = fmaxf(sumsq - nlf * dm * dm, 0.0f);
    float clarity = vs / (nlf - 1.0f);

    int cntTot = (int)(nselF + 0.5f);
    if (cntTot <= 5) {            // cont = 0 -> conf = 0
        if (tid == 0) conf[b] = 0.0f;
        return;
    }

    // Heavy path: stable compaction of bp>0.7 indices + distance variance
    int per = (N + TPB2 - 1) / TPB2;
    int j0 = tid * per;
    int c = 0;
    for (int u = 0; u < per; u++) {
        int j = j0 + u;
        if (j < N && bp[base + j] > 0.7f) c++;
    }
    int lane = tid & 31, warp = tid >> 5;
    int incl = c;
    #pragma unroll
    for (int o = 1; o < 32; o <<= 1) {
        int t = __shfl_up_sync(0xFFFFFFFFu, incl, o);
        if (lane >= o) incl += t;
    }
    if (lane == 31) sIRed[warp] = incl;
    __syncthreads();
    if (warp == 0) {
        int v = sIRed[lane];
        int iv = v;
        #pragma unroll
        for (int o = 1; o < 32; o <<= 1) {
            int t = __shfl_up_sync(0xFFFFFFFFu, iv, o);
            if (lane >= o) iv += t;
        }
        sIRed[lane] = iv - v;
        if (lane == 31) sCnt = iv;
    }
    __syncthreads();
    int cnt = sCnt;

    int r = sIRed[warp] + (incl - c);
    for (int u = 0; u < per; u++) {
        int j = j0 + u;
        if (j < N && bp[base + j] > 0.7f) sSel[r++] = j;
    }
    __syncthreads();

    int P = cnt - 1;              // >= 5
    const float* pb = points + base * 3;
    float sd = 0.0f, sd2 = 0.0f;
    for (int j = tid; j < P; j += TPB2) {
        int ai = sSel[j], e = sSel[j + 1];
        float dx = pb[3 * e]     - pb[3 * ai];
        float dy = pb[3 * e + 1] - pb[3 * ai + 1];
        float dz = pb[3 * e + 2] - pb[3 * ai + 2];
        float dj = sqrtf(dx * dx + dy * dy + dz * dz);
        sd += dj; sd2 += dj * dj;
    }
    sd  = block_reduce_sum(sd, sRed);
    sd2 = block_reduce_sum(sd2, sRed);
    float meanD = sd / (float)P;
    float dvar = fmaxf((sd2 - sd * meanD) / (float)(P - 1), 0.0f);
    float cont = fminf(1.0f / (dvar + 1e-8f), 1.0f);
    float cf = fminf(fmaxf(clarity * cont, 0.0f), 1.0f);
    if (tid == 0) conf[b] = cf;
}

// ---------------------------------------------------------------------------
// Launch: memcpy(features) + compact + mlp(compacted) + stats.
// Graph-capturable, allocation-free.
// Output layout (float32): [boundary_prob B*N][features B*N*F][confidence B]
// ---------------------------------------------------------------------------
extern "C" void kernel_launch(void* const* d_in, const int* in_sizes, int n_in,
                              void* d_out, int out_size)
{
    const float* points   = (const float*)d_in[0];
    const float* features = (const float*)d_in[1];
    const void*  mask     = d_in[2];
    const float* W1 = (const float*)d_in[3];
    const float* b1 = (const float*)d_in[4];
    const float* W2 = (const float*)d_in[5];
    const float* b2 = (const float*)d_in[6];
    const float* W3 = (const float*)d_in[7];
    const float* b3 = (const float*)d_in[8];

    int M = in_sizes[2];                 // B*N total points
    int F = in_sizes[1] / M;             // 64
    long long Bll = (long long)out_size - (long long)M * (1 + F);
    int B = (Bll >= 1 && Bll <= M && (M % (int)Bll) == 0) ? (int)Bll : 4;
    int N = M / B;
    int bpB = (N + TPB1 - 1) / TPB1;     // MLP blocks per batch (all-active cap)

    float* bp = (float*)d_out;
    float* featout = bp + M;
    float* conf = featout + (size_t)M * F;

    size_t smem1 = (size_t)(67 * 64 + 64 * 32 + 64 + 32 + 32 + TPB1 * 65) * sizeof(float)
                 + (size_t)TPB1 * sizeof(int);
    size_t smem2 = (size_t)N * sizeof(int);

    cudaFuncSetAttribute(mlp_kernel, cudaFuncAttributeMaxDynamicSharedMemorySize, (int)smem1);
    cudaFuncSetAttribute(stats_kernel, cudaFuncAttributeMaxDynamicSharedMemorySize, (int)smem2);

    // features pass-through (independent of the kernel chain)
    cudaMemcpyAsync(featout, features, (size_t)M * F * sizeof(float),
                    cudaMemcpyDeviceToDevice);

    compact_kernel<<<B, TPB2>>>(mask, bp, N);
    mlp_kernel<<<B * bpB, TPB1, smem1>>>(points, features,
                                         W1, b1, W2, b2, W3, b3, bp, N, bpB);
    stats_kernel<<<B, TPB2, smem2>>>(points, bp, conf, N, bpB);
}

// round 14
// speedup vs baseline: 1.0887x; 1.0887x over previous
#include <cuda_runtime.h>
#include <math.h>
#include <stdint.h>

#define TPB1 128
#define TPB2 1024
#define TPBC 256
#define IDX_CAP (1 << 22)

// Static device scratch (allocation-free).
__device__ int    g_idx[IDX_CAP];    // per-batch compacted leaf indices (batch-local)
__device__ int    g_cnt[1024];       // per-batch leaf count
__device__ int    g_cntBlk[1 << 15]; // per-(batch,1024-chunk) leaf count
__device__ float4 g_part4[8192];     // per-tile partials {Σs, Σ(s-.5)², nSel, na}
__device__ int    g_ticket;          // MLP work-queue ticket (re-zeroed each replay)

// Padded transposed weight row strides (bank-conflict mitigation)
#define W1T_STRIDE 68   // (68k+j)%32 = (4k+j)%32 -> 4-way instead of 32-way
#define W2T_STRIDE 36   // (36j+i)%32 = (4j+i)%32 -> 4-way instead of 32-way

// ---------------------------------------------------------------------------
// leaf_mask dtype detect (jax bool is dtype-ambiguous), parallel across block:
//   int32 0/1 -> 1, float32 0/1.0 -> 2, uint8 bool -> 0.
// ---------------------------------------------------------------------------
__device__ __forceinline__ int detect_mask_mode_par(const void* m, int tid, int nw) {
    int ok = 1, okf = 1;
    if (tid < nw) {
        unsigned int v = ((const unsigned int*)m)[tid];
        ok  = (v <= 1u);
        okf = (v == 0u || v == 0x3F800000u);
    }
    int allBin   = __syncthreads_and(ok);
    int allFloat = __syncthreads_and(okf);
    return allBin ? 1 : (allFloat ? 2 : 0);
}

__device__ __forceinline__ int read_mask_i(const void* m, size_t i, int mode) {
    if (mode == 1) return ((const int*)m)[i] != 0;
    if (mode == 2) return ((const float*)m)[i] != 0.0f;
    return ((const unsigned char*)m)[i] != 0;
}

// ---------------------------------------------------------------------------
// Kernel A1: per-(batch, 1024-pt chunk) leaf count + zero-fill non-leaf bp.
// grid = B*nbpb, block = 256 (4 consecutive points per thread).
// ---------------------------------------------------------------------------
__global__ void __launch_bounds__(TPBC) count_kernel(
    const void* __restrict__ mask, float* __restrict__ bp, int N, int nbpb)
{
    __shared__ int sW[TPBC / 32];
    int tid = threadIdx.x;
    int b = blockIdx.x / nbpb, blk = blockIdx.x % nbpb;
    size_t base = (size_t)b * N;

    int mode = detect_mask_mode_par(mask, tid, TPBC);   // has barriers

    int i0 = blk * 1024 + tid * 4;
    int c = 0;
    #pragma unroll
    for (int u = 0; u < 4; u++) {
        int i = i0 + u;
        if (i < N) {
            if (read_mask_i(mask, base + i, mode)) c++;
            else bp[base + i] = 0.0f;
        }
    }
    #pragma unroll
    for (int o = 16; o > 0; o >>= 1) c += __shfl_down_sync(0xFFFFFFFFu, c, o);
    if ((tid & 31) == 0) sW[tid >> 5] = c;
    __syncthreads();
    if (tid == 0) {
        int t = 0;
        #pragma unroll
        for (int w = 0; w < TPBC / 32; w++) t += sW[w];
        g_cntBlk[blockIdx.x] = t;
    }
}

// ---------------------------------------------------------------------------
// Kernel A2: stable scatter of leaf indices using per-chunk counts.
// grid = B*nbpb, block = 256. Also writes g_cnt[b] and zeroes the ticket.
// ---------------------------------------------------------------------------
__global__ void __launch_bounds__(TPBC) scatter_kernel(
    const void* __restrict__ mask, int N, int nbpb)
{
    __shared__ int sWS[TPBC / 32];   // warp inclusive sums
    __shared__ int sWB[TPBC / 32];   // warp exclusive bases
    __shared__ int sOff;             // this block's base offset within batch

    int tid = threadIdx.x;
    int b = blockIdx.x / nbpb, blk = blockIdx.x % nbpb;
    size_t base = (size_t)b * N;

    int mode = detect_mask_mode_par(mask, tid, TPBC);   // has barriers

    if (tid == 0) {
        int off = 0, tot = 0;
        for (int j = 0; j < nbpb; j++) {
            int v = g_cntBlk[b * nbpb + j];
            if (j < blk) off += v;
            tot += v;
        }
        sOff = off;
        if (blk == 0) g_cnt[b] = tot;
        if (blockIdx.x == 0) g_ticket = 0;   // reset work queue each replay
    }

    int i0 = blk * 1024 + tid * 4;
    int c = 0;
    #pragma unroll
    for (int u = 0; u < 4; u++) {
        int i = i0 + u;
        if (i < N && read_mask_i(mask, base + i, mode)) c++;
    }
    int lane = tid & 31, warp = tid >> 5;
    int incl = c;
    #pragma unroll
    for (int o = 1; o < 32; o <<= 1) {
        int t = __shfl_up_sync(0xFFFFFFFFu, incl, o);
        if (lane >= o) incl += t;
    }
    if (lane == 31) sWS[warp] = incl;
    __syncthreads();
    if (tid == 0) {
        int acc = 0;
        #pragma unroll
        for (int w = 0; w < TPBC / 32; w++) { sWB[w] = acc; acc += sWS[w]; }
    }
    __syncthreads();

    int r = sOff + sWB[warp] + (incl - c);
    #pragma unroll
    for (int u = 0; u < 4; u++) {
        int i = i0 + u;
        if (i < N && read_mask_i(mask, base + i, mode)) g_idx[base + r++] = i;
    }
}

// ---------------------------------------------------------------------------
// Kernel B: MLP over compacted leaf points, ticket-scheduled for perfect
// load balance. Each dense tile = up to 128 leaf points of one batch.
//   x = [features(64), xyz(3)], h1 = relu(x W1^T+b1), h2 = relu(h1 W2^T+b2),
//   s = sigmoid(h2 W3^T+b3); bp[leaf] = s.
// Partials per tile: {Σs, Σ(s-0.5)², #(s>0.7), na}.
// Tile assignment order is nondeterministic (atomic ticket) but each tile's
// computation and output slots are fixed -> bit-identical results.
// ---------------------------------------------------------------------------
__global__ void __launch_bounds__(TPB1) mlp_kernel(
    const float* __restrict__ points, const float* __restrict__ features,
    const float* __restrict__ W1, const float* __restrict__ b1,
    const float* __restrict__ W2, const float* __restrict__ b2,
    const float* __restrict__ W3, const float* __restrict__ b3,
    float* __restrict__ bp, int N, int B)
{
    extern __shared__ float smem_dyn[];
    float* sW1T = smem_dyn;                    // 67 rows * 68 = 4556
    float* sW2T = sW1T + 67 * W1T_STRIDE;      // 64 rows * 36 = 2304
    float* sB1  = sW2T + 64 * W2T_STRIDE;      // 64
    float* sB2  = sB1 + 64;                    // 32
    float* sW3  = sB2 + 32;                    // 32
    float* sX   = sW3 + 32;                    // 128*65 = 8320
    int*   sIdx = (int*)(sX + TPB1 * 65);      // 128

    __shared__ int sPref[1025];                // per-batch tile prefix (B<=1024)
    __shared__ int sT;
    __shared__ float sb3v;
    __shared__ float3 sPart[TPB1 / 32];

    int tid = threadIdx.x;

    if (tid == 0) {
        int acc = 0;
        for (int bb = 0; bb < B; bb++) {
            sPref[bb] = acc;
            acc += (g_cnt[bb] + TPB1 - 1) / TPB1;
        }
        sPref[B] = acc;
        sT = atomicAdd(&g_ticket, 1);
        sb3v = b3[0];
    }
    __syncthreads();
    int tot = sPref[B];
    int t = sT;
    if (t >= tot) return;                      // no work: skip weight loads

    // Weights (coalesced global reads; padded transposed stores -> 4-way max)
    for (int idx = tid; idx < 64 * 67; idx += TPB1) {
        int j = idx / 67, k = idx % 67;
        sW1T[k * W1T_STRIDE + j] = W1[idx];
    }
    for (int idx = tid; idx < 32 * 64; idx += TPB1) {
        int i = idx >> 6, j = idx & 63;
        sW2T[j * W2T_STRIDE + i] = W2[idx];
    }
    if (tid < 64) sB1[tid] = b1[tid];
    if (tid < 32) { sB2[tid] = b2[tid]; sW3[tid] = W3[tid]; }

    while (t < tot) {
        // map dense tile id -> (batch, chunk)
        int batch = 0;
        while (batch < B - 1 && t >= sPref[batch + 1]) batch++;
        int chunk = t - sPref[batch];
        int cnt = g_cnt[batch];
        int start = chunk * TPB1;
        int na = min(TPB1, cnt - start);
        size_t base = (size_t)batch * N;

        __syncthreads();   // protect sX/sIdx reuse across iterations
        if (tid < na) sIdx[tid] = g_idx[base + start + tid];
        __syncthreads();

        // Stage feature rows of gathered points (float4; 16 thr per 256B row)
        for (int idx = tid; idx < na * 16; idx += TPB1) {
            int r = idx >> 4, c4 = idx & 15;
            const float4 v = ((const float4*)(features + (base + sIdx[r]) * 64))[c4];
            float* d = sX + r * 65 + c4 * 4;
            d[0] = v.x; d[1] = v.y; d[2] = v.z; d[3] = v.w;
        }
        __syncthreads();

        float s = 0.0f;
        int active = (tid < na);
        if (active) {
            const float* row = sX + tid * 65;   // stride 65 -> conflict-free
            int g = sIdx[tid];

            float h1[64];
            #pragma unroll
            for (int j = 0; j < 64; j++) h1[j] = sB1[j];

            #pragma unroll 4
            for (int k = 0; k < 64; k++) {
                float xk = row[k];
                const float4* w4 = (const float4*)&sW1T[k * W1T_STRIDE];
                #pragma unroll
                for (int q = 0; q < 16; q++) {
                    float4 w = w4[q];
                    h1[4 * q + 0] = fmaf(xk, w.x, h1[4 * q + 0]);
                    h1[4 * q + 1] = fmaf(xk, w.y, h1[4 * q + 1]);
                    h1[4 * q + 2] = fmaf(xk, w.z, h1[4 * q + 2]);
                    h1[4 * q + 3] = fmaf(xk, w.w, h1[4 * q + 3]);
                }
            }
            float p0 = points[(base + g) * 3 + 0];
            float p1 = points[(base + g) * 3 + 1];
            float p2 = points[(base + g) * 3 + 2];
            #pragma unroll
            for (int k = 0; k < 3; k++) {
                float xk = (k == 0) ? p0 : (k == 1) ? p1 : p2;
                const float4* w4 = (const float4*)&sW1T[(64 + k) * W1T_STRIDE];
                #pragma unroll
                for (int q = 0; q < 16; q++) {
                    float4 w = w4[q];
                    h1[4 * q + 0] = fmaf(xk, w.x, h1[4 * q + 0]);
                    h1[4 * q + 1] = fmaf(xk, w.y, h1[4 * q + 1]);
                    h1[4 * q + 2] = fmaf(xk, w.z, h1[4 * q + 2]);
                    h1[4 * q + 3] = fmaf(xk, w.w, h1[4 * q + 3]);
                }
            }

            float h2[32];
            #pragma unroll
            for (int i = 0; i < 32; i++) h2[i] = sB2[i];
            #pragma unroll
            for (int j = 0; j < 64; j++) {
                float hj = fmaxf(h1[j], 0.0f);
                const float4* w4 = (const float4*)&sW2T[j * W2T_STRIDE];
                #pragma unroll
                for (int q = 0; q < 8; q++) {
                    float4 w = w4[q];
                    h2[4 * q + 0] = fmaf(hj, w.x, h2[4 * q + 0]);
                    h2[4 * q + 1] = fmaf(hj, w.y, h2[4 * q + 1]);
                    h2[4 * q + 2] = fmaf(hj, w.z, h2[4 * q + 2]);
                    h2[4 * q + 3] = fmaf(hj, w.w, h2[4 * q + 3]);
                }
            }

            float acc = sb3v;
            #pragma unroll
            for (int i = 0; i < 32; i++) acc = fmaf(fmaxf(h2[i], 0.0f), sW3[i], acc);
            s = 1.0f / (1.0f + expf(-acc));
            bp[base + g] = s;      // mask == 1 for compacted points
        }

        // Tile partials: {Σs, Σ(s-0.5)², #(s>0.7)} over active lanes
        {
            float a  = active ? s : 0.0f;
            float d  = active ? (s - 0.5f) : 0.0f;
            float sq = d * d;
            float ns = (active && s > 0.7f) ? 1.0f : 0.0f;
            #pragma unroll
            for (int o = 16; o > 0; o >>= 1) {
                a  += __shfl_down_sync(0xFFFFFFFFu, a, o);
                sq += __shfl_down_sync(0xFFFFFFFFu, sq, o);
                ns += __shfl_down_sync(0xFFFFFFFFu, ns, o);
            }
            int w = tid >> 5, l = tid & 31;
            if (l == 0) sPart[w] = make_float3(a, sq, ns);
            __syncthreads();
            if (tid == 0) {
                float sa = 0.f, sk = 0.f, sn = 0.f;
                #pragma unroll
                for (int ww = 0; ww < TPB1 / 32; ww++) {
                    sa += sPart[ww].x; sk += sPart[ww].y; sn += sPart[ww].z;
                }
                g_part4[t] = make_float4(sa, sk, sn, (float)na);
                sT = atomicAdd(&g_ticket, 1);
            }
        }
        __syncthreads();
        t = sT;
    }
}

// ---------------------------------------------------------------------------
// Block-wide sum over TPB2 threads (uniform call sites only).
// ---------------------------------------------------------------------------
__device__ __forceinline__ float block_reduce_sum(float v, float* scratch) {
    #pragma unroll
    for (int o = 16; o > 0; o >>= 1) v += __shfl_down_sync(0xFFFFFFFFu, v, o);
    int w = threadIdx.x >> 5, l = threadIdx.x & 31;
    if (l == 0) scratch[w] = v;
    __syncthreads();
    if (w == 0) {
        float x = scratch[l];
        #pragma unroll
        for (int o = 16; o > 0; o >>= 1) x += __shfl_down_sync(0xFFFFFFFFu, x, o);
        if (l == 0) scratch[0] = x;
    }
    __syncthreads();
    float r = scratch[0];
    __syncthreads();
    return r;
}

// ---------------------------------------------------------------------------
// Kernel C: per-batch stats from tile partials. Light path (n_leaf<10 or
// cnt<=5) barely touches memory; heavy path (cnt>5) does stable selection +
// single-pass distance variance.
// ---------------------------------------------------------------------------
__global__ void __launch_bounds__(TPB2) stats_kernel(
    const float* __restrict__ points, float* __restrict__ bp,
    float* __restrict__ conf, int N, int B)
{
    extern __shared__ unsigned char smraw[];
    int* sSel = (int*)smraw;                  // N selected indices (heavy path)
    __shared__ float sRed[32];
    __shared__ int   sIRed[32];
    __shared__ int   sCnt;

    int tid = threadIdx.x;
    int b = blockIdx.x;
    size_t base = (size_t)b * N;

    // Dense tile range for this batch (recomputed; cheap)
    int lo = 0;
    for (int bb = 0; bb < b; bb++) lo += (g_cnt[bb] + TPB1 - 1) / TPB1;
    int hi = lo + (g_cnt[b] + TPB1 - 1) / TPB1;

    float a = 0.f, sq = 0.f, ns = 0.f;
    for (int i = lo + tid; i < hi; i += TPB2) {
        float4 p = g_part4[i];
        a += p.x; sq += p.y; ns += p.z;
    }
    float ssum  = block_reduce_sum(a, sRed);
    float sumsq = block_reduce_sum(sq, sRed);
    float nselF = block_reduce_sum(ns, sRed);
    float nlf   = (float)g_cnt[b];

    if (nlf < 10.0f) {
        for (int i = tid; i < N; i += TPB2) bp[base + i] = 0.0f;
        if (tid == 0) conf[b] = 0.0f;
        return;
    }

    // clarity via shifted sums (center 0.5 -> no catastrophic cancellation)
    float mean = ssum / nlf;
    float dm = mean - 0.5f;
    float vs = fmaxf(sumsq - nlf * dm * dm, 0.0f);
    float clarity = vs / (nlf - 1.0f);

    int cntTot = (int)(nselF + 0.5f);
    if (cntTot <= 5) {            // cont = 0 -> conf = 0
        if (tid == 0) conf[b] = 0.0f;
        return;
    }

    // Heavy path: stable compaction of bp>0.7 indices + distance variance
    int per = (N + TPB2 - 1) / TPB2;
    int j0 = tid * per;
    int c = 0;
    for (int u = 0; u < per; u++) {
        int j = j0 + u;
        if (j < N && bp[base + j] > 0.7f) c++;
    }
    int lane = tid & 31, warp = tid >> 5;
    int incl = c;
    #pragma unroll
    for (int o = 1; o < 32; o <<= 1) {
        int t = __shfl_up_sync(0xFFFFFFFFu, incl, o);
        if (lane >= o) incl += t;
    }
    if (lane == 31) sIRed[warp] = incl;
    __syncthreads();
    if (warp == 0) {
        int v = sIRed[lane];
        int iv = v;
        #pragma unroll
        for (int o = 1; o < 32; o <<= 1) {
            int t = __shfl_up_sync(0xFFFFFFFFu, iv, o);
            if (lane >= o) iv += t;
        }
        sIRed[lane] = iv - v;
        if (lane == 31) sCnt = iv;
    }
    __syncthreads();
    int cnt = sCnt;

    int r = sIRed[warp] + (incl - c);
    for (int u = 0; u < per; u++) {
        int j = j0 + u;
        if (j < N && bp[base + j] > 0.7f) sSel[r++] = j;
    }
    __syncthreads();

    int P = cnt - 1;              // >= 5
    const float* pb = points + base * 3;
    float sd = 0.0f, sd2 = 0.0f;
    for (int j = tid; j < P; j += TPB2) {
        int ai = sSel[j], e = sSel[j + 1];
        float dx = pb[3 * e]     - pb[3 * ai];
        float dy = pb[3 * e + 1] - pb[3 * ai + 1];
        float dz = pb[3 * e + 2] - pb[3 * ai + 2];
        float dj = sqrtf(dx * dx + dy * dy + dz * dz);
        sd += dj; sd2 += dj * dj;
    }
    sd  = block_reduce_sum(sd, sRed);
    sd2 = block_reduce_sum(sd2, sRed);
    float meanD = sd / (float)P;
    float dvar = fmaxf((sd2 - sd * meanD) / (float)(P - 1), 0.0f);
    float cont = fminf(1.0f / (dvar + 1e-8f), 1.0f);
    float cf = fminf(fmaxf(clarity * cont, 0.0f), 1.0f);
    if (tid == 0) conf[b] = cf;
}

// ---------------------------------------------------------------------------
// Launch: memcpy(features) + count + scatter + ticketed mlp + stats.
// Graph-capturable, allocation-free.
// Output layout (float32): [boundary_prob B*N][features B*N*F][confidence B]
// ---------------------------------------------------------------------------
extern "C" void kernel_launch(void* const* d_in, const int* in_sizes, int n_in,
                              void* d_out, int out_size)
{
    const float* points   = (const float*)d_in[0];
    const float* features = (const float*)d_in[1];
    const void*  mask     = d_in[2];
    const float* W1 = (const float*)d_in[3];
    const float* b1 = (const float*)d_in[4];
    const float* W2 = (const float*)d_in[5];
    const float* b2 = (const float*)d_in[6];
    const float* W3 = (const float*)d_in[7];
    const float* b3 = (const float*)d_in[8];

    int M = in_sizes[2];                 // B*N total points
    int F = in_sizes[1] / M;             // 64
    long long Bll = (long long)out_size - (long long)M * (1 + F);
    int B = (Bll >= 1 && Bll <= M && (M % (int)Bll) == 0) ? (int)Bll : 4;
    int N = M / B;
    int nbpb = (N + 1023) / 1024;        // 1024-pt chunks per batch

    float* bp = (float*)d_out;
    float* featout = bp + M;
    float* conf = featout + (size_t)M * F;

    size_t smem1 = (size_t)(67 * W1T_STRIDE + 64 * W2T_STRIDE + 64 + 32 + 32
                            + TPB1 * 65) * sizeof(float)
                 + (size_t)TPB1 * sizeof(int);
    size_t smem2 = (size_t)N * sizeof(int);

    cudaFuncSetAttribute(mlp_kernel, cudaFuncAttributeMaxDynamicSharedMemorySize, (int)smem1);
    cudaFuncSetAttribute(stats_kernel, cudaFuncAttributeMaxDynamicSharedMemorySize, (int)smem2);

    // features pass-through (independent of the kernel chain)
    cudaMemcpyAsync(featout, features, (size_t)M * F * sizeof(float),
                    cudaMemcpyDeviceToDevice);

    count_kernel<<<B * nbpb, TPBC>>>(mask, bp, N, nbpb);
    scatter_kernel<<<B * nbpb, TPBC>>>(mask, N, nbpb);
    mlp_kernel<<<296, TPB1, smem1>>>(points, features,
                                     W1, b1, W2, b2, W3, b3, bp, N, B);
    stats_kernel<<<B, TPB2, smem2>>>(points, bp, conf, N, B);
}